// round 1
// baseline (speedup 1.0000x reference)
#include <cuda_runtime.h>

// ImplicitFunction: 8-layer MLP over 1M points, fp32, packed f32x2 FMA path.
//
// Layout per thread: one point; x[64] activations in registers; accumulators
// as 32 x f32x2 (64-bit reg pairs). Per hidden layer the 64x64 weight matrix
// is staged into shared memory (row-major, so a j-pair {w[k][2q],w[k][2q+1]}
// is a naturally aligned 8-byte word) and read broadcast (conflict-free).

#define NTHREADS 256
#define NEG 0.2f

static __device__ __forceinline__ unsigned long long ffma2(
    unsigned long long a, unsigned long long b, unsigned long long c) {
    unsigned long long d;
    asm("fma.rn.f32x2 %0, %1, %2, %3;" : "=l"(d) : "l"(a), "l"(b), "l"(c));
    return d;
}

static __device__ __forceinline__ unsigned long long pack2(float v) {
    unsigned long long d;
    asm("mov.b64 %0, {%1, %1};" : "=l"(d) : "f"(v));
    return d;
}

static __device__ __forceinline__ void unpack2(unsigned long long v, float& lo, float& hi) {
    asm("mov.b64 {%0, %1}, %2;" : "=f"(lo), "=f"(hi) : "l"(v));
}

__global__ __launch_bounds__(NTHREADS, 1)
void implicit_mlp_kernel(const float* __restrict__ points,
                         const float* __restrict__ w0,
                         const float* __restrict__ s0,
                         const float* __restrict__ b0,
                         const float* __restrict__ wh,
                         const float* __restrict__ sh,
                         const float* __restrict__ bh,
                         const float* __restrict__ wo,
                         const float* __restrict__ so,
                         const float* __restrict__ bo,
                         float* __restrict__ out,
                         int n)
{
    __shared__ __align__(16) float wsh[64 * 64];
    __shared__ float ssh[64];
    __shared__ float bsh[64];

    const int tid = threadIdx.x;
    const long long i = (long long)blockIdx.x * NTHREADS + tid;
    const bool valid = (i < (long long)n);

    // ---- stage first-layer params (w0: 3x64, s0, b0) ----
    if (tid < 192) wsh[tid] = w0[tid];
    if (tid < 64) { ssh[tid] = s0[tid]; bsh[tid] = b0[tid]; }
    __syncthreads();

    float p0 = 0.f, p1 = 0.f, p2 = 0.f;
    if (valid) {
        p0 = points[i * 3 + 0];
        p1 = points[i * 3 + 1];
        p2 = points[i * 3 + 2];
    }

    float x[64];
#pragma unroll
    for (int j = 0; j < 64; j++) {
        float a = fmaf(p0, wsh[j], fmaf(p1, wsh[64 + j], p2 * wsh[128 + j]));
        float t = fmaf(a, ssh[j], bsh[j]);
        x[j] = fmaxf(t, NEG * t);   // leakyrelu(0.2), exact since slope < 1
    }

    // ---- 6 hidden layers: x_new = lrelu((x @ W) * s + b) ----
#pragma unroll 1
    for (int l = 0; l < 6; l++) {
        __syncthreads();  // previous compute done before overwriting wsh
        {
            const float4* src = (const float4*)(wh + (size_t)l * 4096);
            float4* dst = (float4*)wsh;
#pragma unroll
            for (int t = 0; t < 4; t++)
                dst[tid + t * NTHREADS] = src[tid + t * NTHREADS];
            if (tid < 64) {
                ssh[tid] = sh[l * 64 + tid];
                bsh[tid] = bh[l * 64 + tid];
            }
        }
        __syncthreads();

        unsigned long long acc[32];
#pragma unroll
        for (int q = 0; q < 32; q++) acc[q] = 0ull;  // {0.f, 0.f}

#pragma unroll
        for (int k = 0; k < 64; k++) {
            const unsigned long long xk2 = pack2(x[k]);
            const ulonglong2* wrow = (const ulonglong2*)(wsh + k * 64);
#pragma unroll
            for (int q = 0; q < 16; q++) {
                ulonglong2 wv = wrow[q];         // LDS.128 broadcast: 4 weights
                acc[2 * q + 0] = ffma2(xk2, wv.x, acc[2 * q + 0]);
                acc[2 * q + 1] = ffma2(xk2, wv.y, acc[2 * q + 1]);
            }
        }

#pragma unroll
        for (int q = 0; q < 32; q++) {
            float a0, a1;
            unpack2(acc[q], a0, a1);
            float t0 = fmaf(a0, ssh[2 * q + 0], bsh[2 * q + 0]);
            float t1 = fmaf(a1, ssh[2 * q + 1], bsh[2 * q + 1]);
            x[2 * q + 0] = fmaxf(t0, NEG * t0);
            x[2 * q + 1] = fmaxf(t1, NEG * t1);
        }
    }

    // ---- output layer: dot(x, wo) * so + bo ----
    __syncthreads();
    if (tid < 64) wsh[tid] = wo[tid];
    __syncthreads();

    // 4 partial chains for ILP in the tail
    float a0 = 0.f, a1 = 0.f, a2 = 0.f, a3 = 0.f;
#pragma unroll
    for (int k = 0; k < 64; k += 4) {
        a0 = fmaf(x[k + 0], wsh[k + 0], a0);
        a1 = fmaf(x[k + 1], wsh[k + 1], a1);
        a2 = fmaf(x[k + 2], wsh[k + 2], a2);
        a3 = fmaf(x[k + 3], wsh[k + 3], a3);
    }
    float acc = (a0 + a1) + (a2 + a3);

    if (valid) out[i] = fmaf(acc, so[0], bo[0]);
}

extern "C" void kernel_launch(void* const* d_in, const int* in_sizes, int n_in,
                              void* d_out, int out_size)
{
    const float* points = (const float*)d_in[0];
    const float* w0     = (const float*)d_in[1];
    const float* s0     = (const float*)d_in[2];
    const float* b0     = (const float*)d_in[3];
    const float* wh     = (const float*)d_in[4];
    const float* sh     = (const float*)d_in[5];
    const float* bh     = (const float*)d_in[6];
    const float* wo     = (const float*)d_in[7];
    const float* so     = (const float*)d_in[8];
    const float* bo     = (const float*)d_in[9];
    float* out = (float*)d_out;

    const int n = in_sizes[0] / 3;   // points is [N, 3]
    const int blocks = (n + NTHREADS - 1) / NTHREADS;

    implicit_mlp_kernel<<<blocks, NTHREADS>>>(
        points, w0, s0, b0, wh, sh, bh, wo, so, bo, out, n);
}

// round 2
// speedup vs baseline: 1.4350x; 1.4350x over previous
#include <cuda_runtime.h>

// ImplicitFunction: 8-layer MLP over 1M points, fp32 via packed f32x2 FMA.
//
// Round-2 structure: each thread owns 2 points and 32 of the 64 output
// columns (lane pairs split columns). Weight LDS traffic is amortized over
// 2 points -> L1 return-path load halves vs round 1 (which was 95% L1-bound).
// Activation halves are exchanged between lane pairs with shfl.xor(1).
//
// SMEM weight layout: row k at k*72 floats; columns 0..31 at +0, columns
// 32..63 at +36 floats (+144B) so the two lane-groups' LDS.128 hit disjoint
// bank sets (plain +128B would be a 2-way conflict).

#define NTHREADS 256
#define NEG 0.2f
#define WROW 72   // padded row stride in floats
#define HOFF 36   // float offset of the upper 32-column half

static __device__ __forceinline__ unsigned long long ffma2(
    unsigned long long a, unsigned long long b, unsigned long long c) {
    unsigned long long d;
    asm("fma.rn.f32x2 %0, %1, %2, %3;" : "=l"(d) : "l"(a), "l"(b), "l"(c));
    return d;
}

static __device__ __forceinline__ unsigned long long pack2(float v) {
    unsigned long long d;
    asm("mov.b64 %0, {%1, %1};" : "=l"(d) : "f"(v));
    return d;
}

static __device__ __forceinline__ void unpack2(unsigned long long v, float& lo, float& hi) {
    asm("mov.b64 {%0, %1}, %2;" : "=f"(lo), "=f"(hi) : "l"(v));
}

static __device__ __forceinline__ float lrelu(float t) {
    return fmaxf(t, NEG * t);
}

__global__ __launch_bounds__(NTHREADS, 1)
void implicit_mlp_kernel(const float* __restrict__ points,
                         const float* __restrict__ w0,
                         const float* __restrict__ s0,
                         const float* __restrict__ b0,
                         const float* __restrict__ wh,
                         const float* __restrict__ sh,
                         const float* __restrict__ bh,
                         const float* __restrict__ wo,
                         const float* __restrict__ so,
                         const float* __restrict__ bo,
                         float* __restrict__ out,
                         int n)
{
    __shared__ __align__(16) float wsh[64 * WROW];
    __shared__ __align__(8) float ssh[64];
    __shared__ __align__(8) float bsh[64];
    __shared__ float w0sh[192];

    const int tid  = threadIdx.x;
    const int h    = tid & 1;            // which 32-column half this lane owns
    const int pair = tid >> 1;
    const long long i0 = (long long)blockIdx.x * (2 * (NTHREADS / 2)) + 2 * pair;
    const long long i1 = i0 + 1;

    // ---- stage first-layer params ----
    if (tid < 192) w0sh[tid] = w0[tid];
    if (tid < 64) { ssh[tid] = s0[tid]; bsh[tid] = b0[tid]; }
    __syncthreads();

    float a0x = 0.f, a0y = 0.f, a0z = 0.f;
    float a1x = 0.f, a1y = 0.f, a1z = 0.f;
    if (i0 < n) { a0x = points[i0 * 3 + 0]; a0y = points[i0 * 3 + 1]; a0z = points[i0 * 3 + 2]; }
    if (i1 < n) { a1x = points[i1 * 3 + 0]; a1y = points[i1 * 3 + 1]; a1z = points[i1 * 3 + 2]; }

    float x0[64], x1[64];   // full activation vectors for both points

    // ---- first layer: each thread computes its 32 columns for both points,
    //      then exchanges with the partner lane to build full vectors ----
    {
        const int jb = h * 32;
#pragma unroll
        for (int c = 0; c < 32; c += 2) {
            float s_lo = ssh[jb + c], s_hi = ssh[jb + c + 1];
            float b_lo = bsh[jb + c], b_hi = bsh[jb + c + 1];
            float w0a = w0sh[jb + c],       w0b = w0sh[jb + c + 1];
            float w1a = w0sh[64 + jb + c],  w1b = w0sh[64 + jb + c + 1];
            float w2a = w0sh[128 + jb + c], w2b = w0sh[128 + jb + c + 1];

            float o00 = lrelu(fmaf(fmaf(a0x, w0a, fmaf(a0y, w1a, a0z * w2a)), s_lo, b_lo));
            float o01 = lrelu(fmaf(fmaf(a0x, w0b, fmaf(a0y, w1b, a0z * w2b)), s_hi, b_hi));
            float o10 = lrelu(fmaf(fmaf(a1x, w0a, fmaf(a1y, w1a, a1z * w2a)), s_lo, b_lo));
            float o11 = lrelu(fmaf(fmaf(a1x, w0b, fmaf(a1y, w1b, a1z * w2b)), s_hi, b_hi));

            float p00 = __shfl_xor_sync(0xffffffffu, o00, 1);
            float p01 = __shfl_xor_sync(0xffffffffu, o01, 1);
            float p10 = __shfl_xor_sync(0xffffffffu, o10, 1);
            float p11 = __shfl_xor_sync(0xffffffffu, o11, 1);

            x0[c]          = h ? p00 : o00;
            x0[c + 1]      = h ? p01 : o01;
            x0[32 + c]     = h ? o00 : p00;
            x0[32 + c + 1] = h ? o01 : p01;
            x1[c]          = h ? p10 : o10;
            x1[c + 1]      = h ? p11 : o11;
            x1[32 + c]     = h ? o10 : p10;
            x1[32 + c + 1] = h ? o11 : p11;
        }
    }

    // ---- 6 hidden layers ----
#pragma unroll 1
    for (int l = 0; l < 6; l++) {
        __syncthreads();   // previous layer's reads of wsh/ssh/bsh done
        {
            // stage 64x64 weights into padded layout (float4 granularity)
            const float4* src = (const float4*)(wh + (size_t)l * 4096);
#pragma unroll
            for (int t = 0; t < 4; t++) {
                int idx4 = tid + t * NTHREADS;      // 0..1023
                int k  = idx4 >> 4;
                int jq = (idx4 & 15) * 4;           // 0,4,...,60 (never straddles 32)
                int dst = k * WROW + ((jq >= 32) ? (HOFF - 32) : 0) + jq;
                *(float4*)&wsh[dst] = src[idx4];
            }
            if (tid < 64) {
                ssh[tid] = sh[l * 64 + tid];
                bsh[tid] = bh[l * 64 + tid];
            }
        }
        __syncthreads();

        unsigned long long acc0[16], acc1[16];
#pragma unroll
        for (int q = 0; q < 16; q++) { acc0[q] = 0ull; acc1[q] = 0ull; }

        const char* wbase = (const char*)wsh + h * (HOFF * 4);
#pragma unroll
        for (int k = 0; k < 64; k++) {
            const unsigned long long xk0 = pack2(x0[k]);
            const unsigned long long xk1 = pack2(x1[k]);
            const ulonglong2* wrow = (const ulonglong2*)(wbase + k * (WROW * 4));
#pragma unroll
            for (int q = 0; q < 8; q++) {
                ulonglong2 wv = wrow[q];   // 4 weights, cols h*32 + 4q..4q+3
                acc0[2 * q + 0] = ffma2(xk0, wv.x, acc0[2 * q + 0]);
                acc0[2 * q + 1] = ffma2(xk0, wv.y, acc0[2 * q + 1]);
                acc1[2 * q + 0] = ffma2(xk1, wv.x, acc1[2 * q + 0]);
                acc1[2 * q + 1] = ffma2(xk1, wv.y, acc1[2 * q + 1]);
            }
        }

        // epilogue: scale/bias/lrelu, then lane-pair exchange to rebuild x
        const int jb = h * 32;
#pragma unroll
        for (int q = 0; q < 16; q++) {
            int c = 2 * q;
            float2 sv = *(const float2*)&ssh[jb + c];
            float2 bv = *(const float2*)&bsh[jb + c];
            float v00, v01, v10, v11;
            unpack2(acc0[q], v00, v01);
            unpack2(acc1[q], v10, v11);
            float o00 = lrelu(fmaf(v00, sv.x, bv.x));
            float o01 = lrelu(fmaf(v01, sv.y, bv.y));
            float o10 = lrelu(fmaf(v10, sv.x, bv.x));
            float o11 = lrelu(fmaf(v11, sv.y, bv.y));

            float p00 = __shfl_xor_sync(0xffffffffu, o00, 1);
            float p01 = __shfl_xor_sync(0xffffffffu, o01, 1);
            float p10 = __shfl_xor_sync(0xffffffffu, o10, 1);
            float p11 = __shfl_xor_sync(0xffffffffu, o11, 1);

            x0[c]          = h ? p00 : o00;
            x0[c + 1]      = h ? p01 : o01;
            x0[32 + c]     = h ? o00 : p00;
            x0[32 + c + 1] = h ? o01 : p01;
            x1[c]          = h ? p10 : o10;
            x1[c + 1]      = h ? p11 : o11;
            x1[32 + c]     = h ? o10 : p10;
            x1[32 + c + 1] = h ? o11 : p11;
        }
    }

    // ---- output layer ----
    __syncthreads();
    if (tid < 64) wsh[tid] = wo[tid];
    __syncthreads();

    float d00 = 0.f, d01 = 0.f, d10 = 0.f, d11 = 0.f;
#pragma unroll
    for (int k = 0; k < 64; k += 2) {
        float wa = wsh[k], wb = wsh[k + 1];
        d00 = fmaf(x0[k], wa, d00);
        d01 = fmaf(x0[k + 1], wb, d01);
        d10 = fmaf(x1[k], wa, d10);
        d11 = fmaf(x1[k + 1], wb, d11);
    }
    float dot0 = d00 + d01;
    float dot1 = d10 + d11;

    const float sov = so[0];
    const float bov = bo[0];
    const long long iw = i0 + h;           // h=0 writes i0, h=1 writes i1
    const float dv = h ? dot1 : dot0;
    if (iw < n) out[iw] = fmaf(dv, sov, bov);
}

extern "C" void kernel_launch(void* const* d_in, const int* in_sizes, int n_in,
                              void* d_out, int out_size)
{
    const float* points = (const float*)d_in[0];
    const float* w0     = (const float*)d_in[1];
    const float* s0     = (const float*)d_in[2];
    const float* b0     = (const float*)d_in[3];
    const float* wh     = (const float*)d_in[4];
    const float* sh     = (const float*)d_in[5];
    const float* bh     = (const float*)d_in[6];
    const float* wo     = (const float*)d_in[7];
    const float* so     = (const float*)d_in[8];
    const float* bo     = (const float*)d_in[9];
    float* out = (float*)d_out;

    const int n = in_sizes[0] / 3;                  // points is [N, 3]
    const int pts_per_block = NTHREADS;             // 128 pairs * 2 points
    const int blocks = (n + pts_per_block - 1) / pts_per_block;

    implicit_mlp_kernel<<<blocks, NTHREADS>>>(
        points, w0, s0, b0, wh, sh, bh, wo, so, bo, out, n);
}

// round 4
// speedup vs baseline: 4.0446x; 2.8186x over previous
#include <cuda_runtime.h>
#include <cstdint>

// ImplicitFunction: hidden 64x64 layers on tensor cores via mma.sync bf16
// (m16n8k16, HMMA path — valid at compute_103), 3-term hi/lo split for fp32-
// class accuracy. Activations stay entirely in registers across all layers
// (D fragment of two n8 tiles == A fragment of one k16 tile).

#define NT 256
#define TILE_M 256
#define NEG 0.2f
#define NLAYER 6

// ---- SMEM layout (byte offsets) ----
#define OFF_WF   0
#define WF_BYTES (NLAYER * 8 * 4 * 32 * 16)   // 98304: [l][nt][kt][lane]{bhi0,bhi1,blo0,blo1}
#define OFF_SH   (OFF_WF + WF_BYTES)
#define OFF_BH   (OFF_SH + 1536)
#define OFF_W0   (OFF_BH + 1536)
#define OFF_S0   (OFF_W0 + 768)
#define OFF_B0   (OFF_S0 + 256)
#define OFF_WO   (OFF_B0 + 256)
#define OFF_SOBO (OFF_WO + 256)
#define SMEM_BYTES (OFF_SOBO + 16)

// weights in mma-fragment order, hi/lo bf16, all 6 hidden layers
__device__ __align__(16) uint32_t g_wfrag[NLAYER * 8 * 4 * 32 * 4];

// ---------------- helpers ----------------
static __device__ __forceinline__ float lrelu(float t) { return fmaxf(t, NEG * t); }

// pack two f32 into bf16x2: element a -> low half, element b -> high half
static __device__ __forceinline__ uint32_t pack_bf16x2(float a, float b) {
    uint32_t r;
    asm("cvt.rn.bf16x2.f32 %0, %1, %2;" : "=r"(r) : "f"(b), "f"(a));
    return r;
}

// hi/lo split of a pair: returns hi-packed reg, writes lo-packed reg
static __device__ __forceinline__ uint32_t split2(float a, float b, uint32_t* lo) {
    uint32_t hi = pack_bf16x2(a, b);
    float ha = __uint_as_float(hi << 16);
    float hb = __uint_as_float(hi & 0xFFFF0000u);
    *lo = pack_bf16x2(a - ha, b - hb);
    return hi;
}

static __device__ __forceinline__ void mma_bf16(float* c, const uint32_t* a,
                                                uint32_t b0, uint32_t b1) {
    asm volatile(
        "mma.sync.aligned.m16n8k16.row.col.f32.bf16.bf16.f32 "
        "{%0,%1,%2,%3}, {%4,%5,%6,%7}, {%8,%9}, {%0,%1,%2,%3};"
        : "+f"(c[0]), "+f"(c[1]), "+f"(c[2]), "+f"(c[3])
        : "r"(a[0]), "r"(a[1]), "r"(a[2]), "r"(a[3]), "r"(b0), "r"(b1));
}

// ---------------- prep: weights -> hi/lo bf16 fragment order ----------------
// B fragment (m16n8k16, col layout): b0: k=(lane%4)*2, n=lane/4; b1: k+1;
// b2: k+8; b3: k+9. reg0 = {b0 lo, b1 hi}, reg1 = {b2 lo, b3 hi}.
__global__ void prep_weights(const float* __restrict__ wh) {
    int t = blockIdx.x * blockDim.x + threadIdx.x;
    if (t >= NLAYER * 8 * 4 * 32) return;
    int lane = t & 31;
    int kt = (t >> 5) & 3;
    int nt = (t >> 7) & 7;
    int l = t >> 10;
    int k0 = kt * 16 + (lane & 3) * 2;
    int nn = nt * 8 + (lane >> 2);
    const float* W = wh + l * 4096;           // W[k][n] row-major
    float w0 = W[k0 * 64 + nn];
    float w1 = W[(k0 + 1) * 64 + nn];
    float w2 = W[(k0 + 8) * 64 + nn];
    float w3 = W[(k0 + 9) * 64 + nn];
    uint32_t l0, l1;
    uint32_t h0 = split2(w0, w1, &l0);
    uint32_t h1 = split2(w2, w3, &l1);
    ((uint4*)g_wfrag)[t] = make_uint4(h0, h1, l0, l1);
}

// ---------------- main kernel ----------------
__global__ __launch_bounds__(NT, 1)
void implicit_mlp_mma(const float* __restrict__ points,
                      const float* __restrict__ w0,
                      const float* __restrict__ s0,
                      const float* __restrict__ b0,
                      const float* __restrict__ sh,
                      const float* __restrict__ bh,
                      const float* __restrict__ wo,
                      const float* __restrict__ so,
                      const float* __restrict__ bo,
                      float* __restrict__ out,
                      int n, int ntiles)
{
    extern __shared__ __align__(16) unsigned char smem[];

    const int tid = threadIdx.x;
    const int wid = tid >> 5;
    const int lane = tid & 31;
    const int tig = lane & 3;       // thread-in-group: column pair selector
    const int grp = lane >> 2;      // group: row selector
    const int cb = tig * 2;         // column base within an n-tile

    // ---- stage weights + params once ----
    {
        const uint4* gsrc = (const uint4*)g_wfrag;
        uint4* gdst = (uint4*)(smem + OFF_WF);
        for (int i = tid; i < WF_BYTES / 16; i += NT) gdst[i] = gsrc[i];
        float* d;
        d = (float*)(smem + OFF_SH); for (int i = tid; i < 384; i += NT) d[i] = sh[i];
        d = (float*)(smem + OFF_BH); for (int i = tid; i < 384; i += NT) d[i] = bh[i];
        d = (float*)(smem + OFF_W0); for (int i = tid; i < 192; i += NT) d[i] = w0[i];
        d = (float*)(smem + OFF_S0); if (tid < 64) d[tid] = s0[tid];
        d = (float*)(smem + OFF_B0); if (tid < 64) d[tid] = b0[tid];
        d = (float*)(smem + OFF_WO); if (tid < 64) d[tid] = wo[tid];
        if (tid == 0) {
            ((float*)(smem + OFF_SOBO))[0] = so[0];
            ((float*)(smem + OFF_SOBO))[1] = bo[0];
        }
    }
    __syncthreads();

    const float* shm_sh = (const float*)(smem + OFF_SH);
    const float* shm_bh = (const float*)(smem + OFF_BH);
    const float* shm_w0 = (const float*)(smem + OFF_W0);
    const float* shm_s0 = (const float*)(smem + OFF_S0);
    const float* shm_b0 = (const float*)(smem + OFF_B0);
    const float* shm_wo = (const float*)(smem + OFF_WO);
    const float so_v = ((const float*)(smem + OFF_SOBO))[0];
    const float bo_v = ((const float*)(smem + OFF_SOBO))[1];
    const uint4* wf_sh = (const uint4*)(smem + OFF_WF);

    for (int tile = blockIdx.x; tile < ntiles; tile += gridDim.x) {
        const long long rowbase = (long long)tile * TILE_M + wid * 32;

        float acc[2][8][4];
        uint32_t Ahi[2][4][4], Alo[2][4][4];

        // ---- layer 0 (K=3) scalar, results placed in D-fragment positions ----
#pragma unroll
        for (int mt = 0; mt < 2; mt++) {
            const long long r0 = rowbase + mt * 16 + grp;
            const long long r1 = r0 + 8;
            float p0x = 0.f, p0y = 0.f, p0z = 0.f, p1x = 0.f, p1y = 0.f, p1z = 0.f;
            if (r0 < n) { p0x = points[r0*3+0]; p0y = points[r0*3+1]; p0z = points[r0*3+2]; }
            if (r1 < n) { p1x = points[r1*3+0]; p1y = points[r1*3+1]; p1z = points[r1*3+2]; }
#pragma unroll
            for (int nt = 0; nt < 8; nt++) {
#pragma unroll
                for (int j = 0; j < 2; j++) {
                    int c = nt * 8 + cb + j;
                    float wa = shm_w0[c], wb = shm_w0[64 + c], wc = shm_w0[128 + c];
                    float sv = shm_s0[c], bv = shm_b0[c];
                    acc[mt][nt][j]     = lrelu(fmaf(fmaf(p0x, wa, fmaf(p0y, wb, p0z * wc)), sv, bv));
                    acc[mt][nt][2 + j] = lrelu(fmaf(fmaf(p1x, wa, fmaf(p1y, wb, p1z * wc)), sv, bv));
                }
            }
        }
        // convert to A fragments (hi/lo)
#pragma unroll
        for (int mt = 0; mt < 2; mt++)
#pragma unroll
            for (int kt = 0; kt < 4; kt++) {
                Ahi[mt][kt][0] = split2(acc[mt][2*kt][0],   acc[mt][2*kt][1],   &Alo[mt][kt][0]);
                Ahi[mt][kt][1] = split2(acc[mt][2*kt][2],   acc[mt][2*kt][3],   &Alo[mt][kt][1]);
                Ahi[mt][kt][2] = split2(acc[mt][2*kt+1][0], acc[mt][2*kt+1][1], &Alo[mt][kt][2]);
                Ahi[mt][kt][3] = split2(acc[mt][2*kt+1][2], acc[mt][2*kt+1][3], &Alo[mt][kt][3]);
            }

        // ---- 6 hidden layers, all-register ----
#pragma unroll
        for (int l = 0; l < NLAYER; l++) {
#pragma unroll
            for (int mt = 0; mt < 2; mt++)
#pragma unroll
                for (int nt = 0; nt < 8; nt++)
#pragma unroll
                    for (int e = 0; e < 4; e++) acc[mt][nt][e] = 0.f;

            const uint4* wl = wf_sh + (l * 32) * 32 + lane;
#pragma unroll
            for (int kt = 0; kt < 4; kt++) {
#pragma unroll
                for (int nt = 0; nt < 8; nt++) {
                    uint4 wf = wl[(nt * 4 + kt) * 32];
#pragma unroll
                    for (int mt = 0; mt < 2; mt++) {
                        mma_bf16(acc[mt][nt], Ahi[mt][kt], wf.x, wf.y);  // hi*hi
                        mma_bf16(acc[mt][nt], Ahi[mt][kt], wf.z, wf.w);  // hi*lo
                        mma_bf16(acc[mt][nt], Alo[mt][kt], wf.x, wf.y);  // lo*hi
                    }
                }
            }

            const float* sl = shm_sh + l * 64;
            const float* bl = shm_bh + l * 64;
            if (l < NLAYER - 1) {
#pragma unroll
                for (int mt = 0; mt < 2; mt++)
#pragma unroll
                    for (int nt = 0; nt < 8; nt++) {
                        int c0 = nt * 8 + cb;
                        float s0v = sl[c0], s1v = sl[c0 + 1];
                        float b0v = bl[c0], b1v = bl[c0 + 1];
                        acc[mt][nt][0] = lrelu(fmaf(acc[mt][nt][0], s0v, b0v));
                        acc[mt][nt][1] = lrelu(fmaf(acc[mt][nt][1], s1v, b1v));
                        acc[mt][nt][2] = lrelu(fmaf(acc[mt][nt][2], s0v, b0v));
                        acc[mt][nt][3] = lrelu(fmaf(acc[mt][nt][3], s1v, b1v));
                    }
#pragma unroll
                for (int mt = 0; mt < 2; mt++)
#pragma unroll
                    for (int kt = 0; kt < 4; kt++) {
                        Ahi[mt][kt][0] = split2(acc[mt][2*kt][0],   acc[mt][2*kt][1],   &Alo[mt][kt][0]);
                        Ahi[mt][kt][1] = split2(acc[mt][2*kt][2],   acc[mt][2*kt][3],   &Alo[mt][kt][1]);
                        Ahi[mt][kt][2] = split2(acc[mt][2*kt+1][0], acc[mt][2*kt+1][1], &Alo[mt][kt][2]);
                        Ahi[mt][kt][3] = split2(acc[mt][2*kt+1][2], acc[mt][2*kt+1][3], &Alo[mt][kt][3]);
                    }
            } else {
                // ---- fused output layer: lrelu -> dot with wo -> lane reduce ----
#pragma unroll
                for (int mt = 0; mt < 2; mt++) {
                    float d0 = 0.f, d1 = 0.f;
#pragma unroll
                    for (int nt = 0; nt < 8; nt++) {
                        int c0 = nt * 8 + cb;
                        float s0v = sl[c0], s1v = sl[c0 + 1];
                        float b0v = bl[c0], b1v = bl[c0 + 1];
                        float w0v = shm_wo[c0], w1v = shm_wo[c0 + 1];
                        d0 = fmaf(lrelu(fmaf(acc[mt][nt][0], s0v, b0v)), w0v, d0);
                        d0 = fmaf(lrelu(fmaf(acc[mt][nt][1], s1v, b1v)), w1v, d0);
                        d1 = fmaf(lrelu(fmaf(acc[mt][nt][2], s0v, b0v)), w0v, d1);
                        d1 = fmaf(lrelu(fmaf(acc[mt][nt][3], s1v, b1v)), w1v, d1);
                    }
                    // reduce across the 4 lanes sharing these rows
                    d0 += __shfl_xor_sync(0xffffffffu, d0, 1);
                    d0 += __shfl_xor_sync(0xffffffffu, d0, 2);
                    d1 += __shfl_xor_sync(0xffffffffu, d1, 1);
                    d1 += __shfl_xor_sync(0xffffffffu, d1, 2);
                    if (tig == 0) {
                        long long r0 = rowbase + mt * 16 + grp;
                        long long r1 = r0 + 8;
                        if (r0 < n) out[r0] = fmaf(d0, so_v, bo_v);
                        if (r1 < n) out[r1] = fmaf(d1, so_v, bo_v);
                    }
                }
            }
        }
    }
}

extern "C" void kernel_launch(void* const* d_in, const int* in_sizes, int n_in,
                              void* d_out, int out_size)
{
    const float* points = (const float*)d_in[0];
    const float* w0     = (const float*)d_in[1];
    const float* s0     = (const float*)d_in[2];
    const float* b0     = (const float*)d_in[3];
    const float* wh     = (const float*)d_in[4];
    const float* sh     = (const float*)d_in[5];
    const float* bh     = (const float*)d_in[6];
    const float* wo     = (const float*)d_in[7];
    const float* so     = (const float*)d_in[8];
    const float* bo     = (const float*)d_in[9];
    float* out = (float*)d_out;

    const int n = in_sizes[0] / 3;
    const int ntiles = (n + TILE_M - 1) / TILE_M;

    prep_weights<<<(NLAYER * 8 * 4 * 32 + 255) / 256, 256>>>(wh);

    int sms = 148;
    cudaDeviceGetAttribute(&sms, cudaDevAttrMultiProcessorCount, 0);
    cudaFuncSetAttribute(implicit_mlp_mma,
                         cudaFuncAttributeMaxDynamicSharedMemorySize, SMEM_BYTES);
    int grid = sms < ntiles ? sms : ntiles;

    implicit_mlp_mma<<<grid, NT, SMEM_BYTES>>>(
        points, w0, s0, b0, sh, bh, wo, so, bo, out, n, ntiles);
}

// round 5
// speedup vs baseline: 4.0944x; 1.0123x over previous
#include <cuda_runtime.h>
#include <cstdint>

// ImplicitFunction: hidden 64x64 layers via mma.sync bf16 m16n8k16, 3-term
// hi/lo split. Round-5: 16 rows/warp, 2 CTAs/SM (4 warps/SMSP), MMA issue
// reordered into 3 passes of 8 independent MMAs (dep distance 1 -> 8).

#define NT 256
#define TILE_M 128          // 8 warps * 16 rows
#define NEG 0.2f
#define NLAYER 6

// ---- SMEM layout (byte offsets) ----
#define OFF_WF   0
#define WF_BYTES (NLAYER * 8 * 4 * 32 * 16)   // 98304
#define OFF_SH   (OFF_WF + WF_BYTES)
#define OFF_BH   (OFF_SH + 1536)
#define OFF_W0   (OFF_BH + 1536)
#define OFF_S0   (OFF_W0 + 768)
#define OFF_B0   (OFF_S0 + 256)
#define OFF_WO   (OFF_B0 + 256)
#define OFF_SOBO (OFF_WO + 256)
#define SMEM_BYTES (OFF_SOBO + 16)

__device__ __align__(16) uint32_t g_wfrag[NLAYER * 8 * 4 * 32 * 4];

static __device__ __forceinline__ float lrelu(float t) { return fmaxf(t, NEG * t); }

static __device__ __forceinline__ uint32_t pack_bf16x2(float a, float b) {
    uint32_t r;
    asm("cvt.rn.bf16x2.f32 %0, %1, %2;" : "=r"(r) : "f"(b), "f"(a));
    return r;
}
static __device__ __forceinline__ uint32_t split2(float a, float b, uint32_t* lo) {
    uint32_t hi = pack_bf16x2(a, b);
    float ha = __uint_as_float(hi << 16);
    float hb = __uint_as_float(hi & 0xFFFF0000u);
    *lo = pack_bf16x2(a - ha, b - hb);
    return hi;
}
static __device__ __forceinline__ void mma_bf16(float* c, const uint32_t* a,
                                                uint32_t b0, uint32_t b1) {
    asm volatile(
        "mma.sync.aligned.m16n8k16.row.col.f32.bf16.bf16.f32 "
        "{%0,%1,%2,%3}, {%4,%5,%6,%7}, {%8,%9}, {%0,%1,%2,%3};"
        : "+f"(c[0]), "+f"(c[1]), "+f"(c[2]), "+f"(c[3])
        : "r"(a[0]), "r"(a[1]), "r"(a[2]), "r"(a[3]), "r"(b0), "r"(b1));
}

// prep: weights -> hi/lo bf16 fragment order (unchanged from round 4)
__global__ void prep_weights(const float* __restrict__ wh) {
    int t = blockIdx.x * blockDim.x + threadIdx.x;
    if (t >= NLAYER * 8 * 4 * 32) return;
    int lane = t & 31;
    int kt = (t >> 5) & 3;
    int nt = (t >> 7) & 7;
    int l = t >> 10;
    int k0 = kt * 16 + (lane & 3) * 2;
    int nn = nt * 8 + (lane >> 2);
    const float* W = wh + l * 4096;
    float w0 = W[k0 * 64 + nn];
    float w1 = W[(k0 + 1) * 64 + nn];
    float w2 = W[(k0 + 8) * 64 + nn];
    float w3 = W[(k0 + 9) * 64 + nn];
    uint32_t l0, l1;
    uint32_t h0 = split2(w0, w1, &l0);
    uint32_t h1 = split2(w2, w3, &l1);
    ((uint4*)g_wfrag)[t] = make_uint4(h0, h1, l0, l1);
}

__global__ __launch_bounds__(NT, 2)
void implicit_mlp_mma(const float* __restrict__ points,
                      const float* __restrict__ w0,
                      const float* __restrict__ s0,
                      const float* __restrict__ b0,
                      const float* __restrict__ sh,
                      const float* __restrict__ bh,
                      const float* __restrict__ wo,
                      const float* __restrict__ so,
                      const float* __restrict__ bo,
                      float* __restrict__ out,
                      int n, int ntiles)
{
    extern __shared__ __align__(16) unsigned char smem[];

    const int tid = threadIdx.x;
    const int wid = tid >> 5;
    const int lane = tid & 31;
    const int tig = lane & 3;
    const int grp = lane >> 2;
    const int cb = tig * 2;

    {
        const uint4* gsrc = (const uint4*)g_wfrag;
        uint4* gdst = (uint4*)(smem + OFF_WF);
        for (int i = tid; i < WF_BYTES / 16; i += NT) gdst[i] = gsrc[i];
        float* d;
        d = (float*)(smem + OFF_SH); for (int i = tid; i < 384; i += NT) d[i] = sh[i];
        d = (float*)(smem + OFF_BH); for (int i = tid; i < 384; i += NT) d[i] = bh[i];
        d = (float*)(smem + OFF_W0); for (int i = tid; i < 192; i += NT) d[i] = w0[i];
        d = (float*)(smem + OFF_S0); if (tid < 64) d[tid] = s0[tid];
        d = (float*)(smem + OFF_B0); if (tid < 64) d[tid] = b0[tid];
        d = (float*)(smem + OFF_WO); if (tid < 64) d[tid] = wo[tid];
        if (tid == 0) {
            ((float*)(smem + OFF_SOBO))[0] = so[0];
            ((float*)(smem + OFF_SOBO))[1] = bo[0];
        }
    }
    __syncthreads();

    const float* shm_sh = (const float*)(smem + OFF_SH);
    const float* shm_bh = (const float*)(smem + OFF_BH);
    const float* shm_w0 = (const float*)(smem + OFF_W0);
    const float* shm_s0 = (const float*)(smem + OFF_S0);
    const float* shm_b0 = (const float*)(smem + OFF_B0);
    const float* shm_wo = (const float*)(smem + OFF_WO);
    const float so_v = ((const float*)(smem + OFF_SOBO))[0];
    const float bo_v = ((const float*)(smem + OFF_SOBO))[1];
    const uint4* wf_sh = (const uint4*)(smem + OFF_WF);

    for (int tile = blockIdx.x; tile < ntiles; tile += gridDim.x) {
        const long long r0 = (long long)tile * TILE_M + wid * 16 + grp;
        const long long r1 = r0 + 8;

        float acc[8][4];
        uint32_t Ahi[4][4], Alo[4][4];

        // ---- layer 0 (K=3) scalar ----
        {
            float p0x = 0.f, p0y = 0.f, p0z = 0.f, p1x = 0.f, p1y = 0.f, p1z = 0.f;
            if (r0 < n) { p0x = points[r0*3+0]; p0y = points[r0*3+1]; p0z = points[r0*3+2]; }
            if (r1 < n) { p1x = points[r1*3+0]; p1y = points[r1*3+1]; p1z = points[r1*3+2]; }
#pragma unroll
            for (int nt = 0; nt < 8; nt++) {
#pragma unroll
                for (int j = 0; j < 2; j++) {
                    int c = nt * 8 + cb + j;
                    float wa = shm_w0[c], wb = shm_w0[64 + c], wc = shm_w0[128 + c];
                    float sv = shm_s0[c], bv = shm_b0[c];
                    acc[nt][j]     = lrelu(fmaf(fmaf(p0x, wa, fmaf(p0y, wb, p0z * wc)), sv, bv));
                    acc[nt][2 + j] = lrelu(fmaf(fmaf(p1x, wa, fmaf(p1y, wb, p1z * wc)), sv, bv));
                }
            }
        }
#pragma unroll
        for (int kt = 0; kt < 4; kt++) {
            Ahi[kt][0] = split2(acc[2*kt][0],   acc[2*kt][1],   &Alo[kt][0]);
            Ahi[kt][1] = split2(acc[2*kt][2],   acc[2*kt][3],   &Alo[kt][1]);
            Ahi[kt][2] = split2(acc[2*kt+1][0], acc[2*kt+1][1], &Alo[kt][2]);
            Ahi[kt][3] = split2(acc[2*kt+1][2], acc[2*kt+1][3], &Alo[kt][3]);
        }

        // ---- 6 hidden layers, all-register, 3-pass MMA issue ----
#pragma unroll
        for (int l = 0; l < NLAYER; l++) {
#pragma unroll
            for (int nt = 0; nt < 8; nt++)
#pragma unroll
                for (int e = 0; e < 4; e++) acc[nt][e] = 0.f;

            const uint4* wl = wf_sh + l * 1024 + lane;
#pragma unroll
            for (int kt = 0; kt < 4; kt++) {
                uint4 wf[8];
#pragma unroll
                for (int nt = 0; nt < 8; nt++) wf[nt] = wl[(nt * 4 + kt) * 32];
                // pass 1: hi*hi (8 independent MMAs)
#pragma unroll
                for (int nt = 0; nt < 8; nt++) mma_bf16(acc[nt], Ahi[kt], wf[nt].x, wf[nt].y);
                // pass 2: hi*lo
#pragma unroll
                for (int nt = 0; nt < 8; nt++) mma_bf16(acc[nt], Ahi[kt], wf[nt].z, wf[nt].w);
                // pass 3: lo*hi
#pragma unroll
                for (int nt = 0; nt < 8; nt++) mma_bf16(acc[nt], Alo[kt], wf[nt].x, wf[nt].y);
            }

            const float* sl = shm_sh + l * 64;
            const float* bl = shm_bh + l * 64;
            if (l < NLAYER - 1) {
#pragma unroll
                for (int nt = 0; nt < 8; nt++) {
                    int c0 = nt * 8 + cb;
                    float s0v = sl[c0], s1v = sl[c0 + 1];
                    float b0v = bl[c0], b1v = bl[c0 + 1];
                    acc[nt][0] = lrelu(fmaf(acc[nt][0], s0v, b0v));
                    acc[nt][1] = lrelu(fmaf(acc[nt][1], s1v, b1v));
                    acc[nt][2] = lrelu(fmaf(acc[nt][2], s0v, b0v));
                    acc[nt][3] = lrelu(fmaf(acc[nt][3], s1v, b1v));
                }
#pragma unroll
                for (int kt = 0; kt < 4; kt++) {
                    Ahi[kt][0] = split2(acc[2*kt][0],   acc[2*kt][1],   &Alo[kt][0]);
                    Ahi[kt][1] = split2(acc[2*kt][2],   acc[2*kt][3],   &Alo[kt][1]);
                    Ahi[kt][2] = split2(acc[2*kt+1][0], acc[2*kt+1][1], &Alo[kt][2]);
                    Ahi[kt][3] = split2(acc[2*kt+1][2], acc[2*kt+1][3], &Alo[kt][3]);
                }
            } else {
                float d0 = 0.f, d1 = 0.f;
#pragma unroll
                for (int nt = 0; nt < 8; nt++) {
                    int c0 = nt * 8 + cb;
                    float s0v = sl[c0], s1v = sl[c0 + 1];
                    float b0v = bl[c0], b1v = bl[c0 + 1];
                    float w0v = shm_wo[c0], w1v = shm_wo[c0 + 1];
                    d0 = fmaf(lrelu(fmaf(acc[nt][0], s0v, b0v)), w0v, d0);
                    d0 = fmaf(lrelu(fmaf(acc[nt][1], s1v, b1v)), w1v, d0);
                    d1 = fmaf(lrelu(fmaf(acc[nt][2], s0v, b0v)), w0v, d1);
                    d1 = fmaf(lrelu(fmaf(acc[nt][3], s1v, b1v)), w1v, d1);
                }
                d0 += __shfl_xor_sync(0xffffffffu, d0, 1);
                d0 += __shfl_xor_sync(0xffffffffu, d0, 2);
                d1 += __shfl_xor_sync(0xffffffffu, d1, 1);
                d1 += __shfl_xor_sync(0xffffffffu, d1, 2);
                if (tig == 0) {
                    if (r0 < n) out[r0] = fmaf(d0, so_v, bo_v);
                    if (r1 < n) out[r1] = fmaf(d1, so_v, bo_v);
                }
            }
        }
    }
}

extern "C" void kernel_launch(void* const* d_in, const int* in_sizes, int n_in,
                              void* d_out, int out_size)
{
    const float* points = (const float*)d_in[0];
    const float* w0     = (const float*)d_in[1];
    const float* s0     = (const float*)d_in[2];
    const float* b0     = (const float*)d_in[3];
    const float* wh     = (const float*)d_in[4];
    const float* sh     = (const float*)d_in[5];
    const float* bh     = (const float*)d_in[6];
    const float* wo     = (const float*)d_in[7];
    const float* so     = (const float*)d_in[8];
    const float* bo     = (const float*)d_in[9];
    float* out = (float*)d_out;

    const int n = in_sizes[0] / 3;
    const int ntiles = (n + TILE_M - 1) / TILE_M;

    prep_weights<<<(NLAYER * 8 * 4 * 32 + 255) / 256, 256>>>(wh);

    int sms = 148;
    cudaDeviceGetAttribute(&sms, cudaDevAttrMultiProcessorCount, 0);
    cudaFuncSetAttribute(implicit_mlp_mma,
                         cudaFuncAttributeMaxDynamicSharedMemorySize, SMEM_BYTES);
    int grid = 2 * sms < ntiles ? 2 * sms : ntiles;

    implicit_mlp_mma<<<grid, NT, SMEM_BYTES>>>(
        points, w0, s0, b0, sh, bh, wo, so, bo, out, n, ntiles);
}